// round 2
// baseline (speedup 1.0000x reference)
#include <cuda_runtime.h>
#include <cuda_bf16.h>
#include <math_constants.h>

#define NPTS 16384
#define MCTR 4096
#define KNBR 32
#define FIN  64
#define RAD2 0.25f
#define MAXC 64

#define G    32      // FPS blocks (co-resident, << SM count)
#define TFPS 512     // threads per FPS block; G*TFPS == NPTS (1 point/thread)

// ---------------- device scratch (no allocations allowed) ----------------
__device__ int g_idx[MCTR];
__device__ int g_nbr[MCTR * KNBR];
__device__ int g_cnt[MCTR];

// FPS exchange slots, double-buffered by iteration parity.
// g_pk : ((u64)bits(val) << 32) | (0xffffffff - idx)   (max key = max val, then min idx)
// g_pxy: (bits(x) << 32) | bits(y)
// g_pzt: (bits(z) << 32) | iteration_tag              (tag written last, after fence)
__device__ unsigned long long g_pk [2][G];
__device__ unsigned long long g_pxy[2][G];
__device__ unsigned long long g_pzt[2][G];

__global__ void fps_init_kernel()
{
    int t = threadIdx.x;
    if (t < G) {
        g_pzt[0][t] = 0xFFFFFFFFull;   // tag = 0xffffffff : never matches it in [1,4095]
        g_pzt[1][t] = 0xFFFFFFFFull;
    }
    if (t == 0) g_idx[0] = 0;
}

// ---------------- Stage 1: cooperative multi-SM FPS ----------------
__global__ __launch_bounds__(TFPS, 1)
void fps_kernel(const float* __restrict__ pos)
{
    __shared__ float    s_c[3];
    __shared__ unsigned s_wv[TFPS / 32];
    __shared__ int      s_wi[TFPS / 32];
    __shared__ float    s_wx[TFPS / 32], s_wy[TFPS / 32], s_wz[TFPS / 32];

    const int t    = threadIdx.x;
    const int bid  = blockIdx.x;
    const int w    = t >> 5;
    const int lane = t & 31;
    const int gi   = bid * TFPS + t;          // this thread's point id

    const float px = pos[gi * 3 + 0];
    const float py = pos[gi * 3 + 1];
    const float pz = pos[gi * 3 + 2];
    float dmin = CUDART_INF_F;

    if (t == 0) { s_c[0] = pos[0]; s_c[1] = pos[1]; s_c[2] = pos[2]; }
    __syncthreads();

    for (int it = 1; it < MCTR; ++it) {
        const int p = it & 1;

        // exact reference arithmetic: ((dx*dx + dy*dy) + dz*dz), all rn, no FMA
        float dx = px - s_c[0], dy = py - s_c[1], dz = pz - s_c[2];
        float d = __fadd_rn(__fadd_rn(__fmul_rn(dx, dx), __fmul_rn(dy, dy)),
                            __fmul_rn(dz, dz));
        dmin = fminf(dmin, d);

        // warp argmax: max value (nonneg float bits monotone as u32), then min index
        unsigned vb   = __float_as_uint(dmin);
        unsigned wmax = __reduce_max_sync(0xffffffffu, vb);
        int cand = (vb == wmax) ? gi : 0x7fffffff;
        int wi   = __reduce_min_sync(0xffffffffu, cand);
        // winner's coords live in lane (wi & 31) of this warp
        int wl = wi & 31;
        float wx = __shfl_sync(0xffffffffu, px, wl);
        float wy = __shfl_sync(0xffffffffu, py, wl);
        float wz = __shfl_sync(0xffffffffu, pz, wl);
        if (lane == 0) {
            s_wv[w] = wmax; s_wi[w] = wi;
            s_wx[w] = wx;   s_wy[w] = wy; s_wz[w] = wz;
        }
        __syncthreads();   // A: per-warp partials ready

        if (w == 0) {
            // block-level reduce over 16 warp partials
            unsigned v  = (lane < TFPS / 32) ? s_wv[lane] : 0u;
            int      i2 = (lane < TFPS / 32) ? s_wi[lane] : 0x7fffffff;
            unsigned bmax = __reduce_max_sync(0xffffffffu, v);
            int c2 = (v == bmax) ? i2 : 0x7fffffff;
            int bi = __reduce_min_sync(0xffffffffu, c2);
            int c3 = (v == bmax && i2 == bi) ? lane : 63;
            int l2 = __reduce_min_sync(0xffffffffu, c3);
            float bx = __shfl_sync(0xffffffffu, (lane < TFPS / 32) ? s_wx[lane] : 0.f, l2);
            float by = __shfl_sync(0xffffffffu, (lane < TFPS / 32) ? s_wy[lane] : 0.f, l2);
            float bz = __shfl_sync(0xffffffffu, (lane < TFPS / 32) ? s_wz[lane] : 0.f, l2);

            if (lane == 0) {
                unsigned long long key =
                    ((unsigned long long)bmax << 32) | (unsigned)(0xffffffffu - (unsigned)bi);
                unsigned long long xy =
                    ((unsigned long long)__float_as_uint(bx) << 32) | __float_as_uint(by);
                asm volatile("st.volatile.global.u64 [%0], %1;"
                             :: "l"(&g_pk[p][bid]),  "l"(key) : "memory");
                asm volatile("st.volatile.global.u64 [%0], %1;"
                             :: "l"(&g_pxy[p][bid]), "l"(xy)  : "memory");
                __threadfence();
                unsigned long long zt =
                    ((unsigned long long)__float_as_uint(bz) << 32) | (unsigned)it;
                asm volatile("st.volatile.global.u64 [%0], %1;"
                             :: "l"(&g_pzt[p][bid]), "l"(zt)  : "memory");
            }

            // every block reduces all G partials itself (no central reducer roundtrip)
            unsigned long long zt;
            do {
                asm volatile("ld.volatile.global.u64 %0, [%1];"
                             : "=l"(zt) : "l"(&g_pzt[p][lane]) : "memory");
            } while ((unsigned)zt != (unsigned)it);
            __threadfence();
            unsigned long long key, xy;
            asm volatile("ld.volatile.global.u64 %0, [%1];"
                         : "=l"(key) : "l"(&g_pk[p][lane]) : "memory");
            asm volatile("ld.volatile.global.u64 %0, [%1];"
                         : "=l"(xy)  : "l"(&g_pxy[p][lane]) : "memory");

            unsigned vb2  = (unsigned)(key >> 32);
            unsigned gmax = __reduce_max_sync(0xffffffffu, vb2);
            unsigned inv  = (vb2 == gmax) ? (unsigned)key : 0u;      // 0xffffffff - idx
            unsigned ginv = __reduce_max_sync(0xffffffffu, inv);     // -> min idx
            int gbi = (int)(0xffffffffu - ginv);
            int c4  = (vb2 == gmax && (unsigned)key == ginv) ? lane : 63;
            int l3  = __reduce_min_sync(0xffffffffu, c4);
            float cx = __shfl_sync(0xffffffffu, __uint_as_float((unsigned)(xy  >> 32)), l3);
            float cy = __shfl_sync(0xffffffffu, __uint_as_float((unsigned)xy),          l3);
            float cz = __shfl_sync(0xffffffffu, __uint_as_float((unsigned)(zt  >> 32)), l3);
            if (lane == 0) {
                s_c[0] = cx; s_c[1] = cy; s_c[2] = cz;
                if (bid == 0) g_idx[it] = gbi;
            }
        }
        __syncthreads();   // B: new center visible to all warps
    }
}

// ---------------- Stage 2: ball query ----------------
#define CHUNK 2048
__global__ __launch_bounds__(256)
void nbr_kernel(const float* __restrict__ pos)
{
    __shared__ float sx[CHUNK], sy[CHUNK], sz[CHUNK];
    __shared__ int   s_ci[8][MAXC];
    __shared__ float s_cd[8][MAXC];

    const int tid  = threadIdx.x;
    const int w    = tid >> 5;
    const int lane = tid & 31;
    const int m    = blockIdx.x * 8 + w;

    const int cidx = g_idx[m];
    const float cx = pos[cidx * 3 + 0];
    const float cy = pos[cidx * 3 + 1];
    const float cz = pos[cidx * 3 + 2];

    int cnt = 0;
    for (int base = 0; base < NPTS; base += CHUNK) {
        __syncthreads();
        for (int i = tid; i < CHUNK; i += 256) {
            sx[i] = pos[(base + i) * 3 + 0];
            sy[i] = pos[(base + i) * 3 + 1];
            sz[i] = pos[(base + i) * 3 + 2];
        }
        __syncthreads();
        for (int i = lane; i < CHUNK; i += 32) {
            float dx = sx[i] - cx, dy = sy[i] - cy, dz = sz[i] - cz;
            float d2 = __fadd_rn(__fadd_rn(__fmul_rn(dx, dx), __fmul_rn(dy, dy)),
                                 __fmul_rn(dz, dz));
            bool in = (d2 <= RAD2);
            unsigned mk = __ballot_sync(0xffffffffu, in);
            int slot = cnt + __popc(mk & ((1u << lane) - 1u));
            if (in && slot < MAXC) { s_ci[w][slot] = base + i; s_cd[w][slot] = d2; }
            cnt += __popc(mk);
        }
    }
    cnt = min(cnt, MAXC);

    if (cnt <= KNBR) {
        if (lane < cnt) g_nbr[m * KNBR + lane] = s_ci[w][lane];
        if (lane == 0)  g_cnt[m] = cnt;
    } else {
        for (int c = lane; c < cnt; c += 32) {
            float d = s_cd[w][c];
            int  ii = s_ci[w][c];
            int r = 0;
            for (int o = 0; o < cnt; ++o) {
                float d2o = s_cd[w][o];
                r += (d2o < d) || (d2o == d && s_ci[w][o] < ii);
            }
            if (r < KNBR) g_nbr[m * KNBR + r] = ii;
        }
        if (lane == 0) g_cnt[m] = KNBR;
    }
}

// ---------------- Stage 3: per-edge MLP + masked max aggregation ----------------
__global__ __launch_bounds__(256)
void mlp_kernel(const float* __restrict__ feat,
                const float* __restrict__ pos,
                const float* __restrict__ W1, const float* __restrict__ b1,
                const float* __restrict__ W2, const float* __restrict__ b2,
                const float* __restrict__ W3, const float* __restrict__ b3,
                float* __restrict__ out)
{
    __shared__ float xb[32][68];
    __shared__ float h1[32][64];
    __shared__ float h2[32][64];
    __shared__ float h3[32][128];

    const int m    = blockIdx.x;
    const int tid  = threadIdx.x;
    const int w    = tid >> 5;
    const int lane = tid & 31;
    const int cnt  = g_cnt[m];

    const int cidx = g_idx[m];
    const float cx = pos[cidx * 3 + 0];
    const float cy = pos[cidx * 3 + 1];
    const float cz = pos[cidx * 3 + 2];

    for (int k = w; k < cnt; k += 8) {
        int j = g_nbr[m * KNBR + k];
        xb[k][lane]      = feat[j * FIN + lane];
        xb[k][lane + 32] = feat[j * FIN + lane + 32];
        if (lane == 0) {
            xb[k][64] = pos[j * 3 + 0] - cx;
            xb[k][65] = pos[j * 3 + 1] - cy;
            xb[k][66] = pos[j * 3 + 2] - cz;
        }
    }
    __syncthreads();

    for (int p = tid; p < cnt * 64; p += 256) {
        int k = p >> 6, o = p & 63;
        float acc = b1[o];
        #pragma unroll
        for (int i = 0; i < 67; ++i)
            acc = fmaf(xb[k][i], W1[i * 64 + o], acc);
        h1[k][o] = fmaxf(acc, 0.0f);
    }
    __syncthreads();

    for (int p = tid; p < cnt * 64; p += 256) {
        int k = p >> 6, o = p & 63;
        float acc = b2[o];
        #pragma unroll
        for (int i = 0; i < 64; ++i)
            acc = fmaf(h1[k][i], W2[i * 64 + o], acc);
        h2[k][o] = fmaxf(acc, 0.0f);
    }
    __syncthreads();

    for (int p = tid; p < cnt * 128; p += 256) {
        int k = p >> 7, o = p & 127;
        float acc = b3[o];
        #pragma unroll
        for (int i = 0; i < 64; ++i)
            acc = fmaf(h2[k][i], W3[i * 128 + o], acc);
        h3[k][o] = fmaxf(acc, 0.0f);
    }
    __syncthreads();

    if (tid < 128) {
        float mx = -CUDART_INF_F;
        for (int k = 0; k < cnt; ++k) mx = fmaxf(mx, h3[k][tid]);
        out[m * 128 + tid] = mx;
    }
}

// ---------------- Stage 4: tail outputs ----------------
__global__ void tail_kernel(const float* __restrict__ pos, float* __restrict__ out,
                            int out_size)
{
    int m = blockIdx.x * blockDim.x + threadIdx.x;
    if (m >= MCTR) return;
    const int base = MCTR * 128;
    if (out_size >= base + 3 * MCTR) {
        int j = g_idx[m];
        out[base + 3 * m + 0] = pos[3 * j + 0];
        out[base + 3 * m + 1] = pos[3 * j + 1];
        out[base + 3 * m + 2] = pos[3 * j + 2];
    }
    if (out_size >= base + 3 * MCTR + MCTR) {
        out[base + 3 * MCTR + m] = 0.0f;
    }
}

extern "C" void kernel_launch(void* const* d_in, const int* in_sizes, int n_in,
                              void* d_out, int out_size)
{
    const float* feat = (const float*)d_in[0];
    const float* pos  = (const float*)d_in[1];
    const float* W1 = (const float*)d_in[3];
    const float* b1 = (const float*)d_in[4];
    const float* W2 = (const float*)d_in[5];
    const float* b2 = (const float*)d_in[6];
    const float* W3 = (const float*)d_in[7];
    const float* b3 = (const float*)d_in[8];
    float* out = (float*)d_out;

    fps_init_kernel<<<1, 32>>>();
    fps_kernel<<<G, TFPS>>>(pos);
    nbr_kernel<<<MCTR / 8, 256>>>(pos);
    mlp_kernel<<<MCTR, 256>>>(feat, pos, W1, b1, W2, b2, W3, b3, out);
    tail_kernel<<<(MCTR + 255) / 256, 256>>>(pos, out, out_size);
}

// round 4
// speedup vs baseline: 1.9937x; 1.9937x over previous
#include <cuda_runtime.h>
#include <cuda_bf16.h>
#include <math_constants.h>

#define NPTS 16384
#define MCTR 4096
#define KNBR 32
#define FIN  64
#define RAD2 0.25f
#define MAXC 64

#define G    16      // FPS blocks (co-resident)
#define TFPS 1024    // threads per FPS block; G*TFPS == NPTS (1 point/thread)

// ---------------- device scratch (no allocations allowed) ----------------
__device__ int g_idx[MCTR];
__device__ int g_nbr[MCTR * KNBR];
__device__ int g_cnt[MCTR];

// FPS exchange: one 128-byte line per (parity, block) slot to kill false sharing.
//   word0 = ((u64)bits(val) << 32) | (0xffffffff - idx)    (max key = max val, min idx)
//   word1 = (bits(x) << 32) | bits(y)
//   word2 = (bits(z) << 32) | iteration_tag                (released last)
__device__ __align__(128) unsigned long long g_slot[2][G][16];

__global__ void fps_init_kernel()
{
    int t = threadIdx.x;
    if (t < G) {
        g_slot[0][t][0] = 0; g_slot[0][t][1] = 0;
        g_slot[1][t][0] = 0; g_slot[1][t][1] = 0;
        g_slot[0][t][2] = 0xFFFFFFFFull;   // tag never matches it in [1,4095]
        g_slot[1][t][2] = 0xFFFFFFFFull;
    }
    if (t == 0) g_idx[0] = 0;
}

__device__ __forceinline__ void st_relaxed_u64(unsigned long long* p, unsigned long long v)
{
    asm volatile("st.relaxed.gpu.global.u64 [%0], %1;" :: "l"(p), "l"(v) : "memory");
}
__device__ __forceinline__ void st_release_u64(unsigned long long* p, unsigned long long v)
{
    asm volatile("st.release.gpu.global.u64 [%0], %1;" :: "l"(p), "l"(v) : "memory");
}
__device__ __forceinline__ unsigned long long ld_acquire_u64(const unsigned long long* p)
{
    unsigned long long v;
    asm volatile("ld.acquire.gpu.global.u64 %0, [%1];" : "=l"(v) : "l"(p) : "memory");
    return v;
}
__device__ __forceinline__ unsigned long long ld_relaxed_u64(const unsigned long long* p)
{
    unsigned long long v;
    asm volatile("ld.relaxed.gpu.global.u64 %0, [%1];" : "=l"(v) : "l"(p) : "memory");
    return v;
}

// ---------------- Stage 1: cooperative multi-SM FPS ----------------
__global__ __launch_bounds__(TFPS, 1)
void fps_kernel(const float* __restrict__ pos)
{
    __shared__ float    s_c[3];
    __shared__ unsigned s_wv[32];
    __shared__ int      s_wi[32];
    __shared__ float    s_wx[32], s_wy[32], s_wz[32];

    const int t    = threadIdx.x;
    const int bid  = blockIdx.x;
    const int w    = t >> 5;
    const int lane = t & 31;
    const int gi   = bid * TFPS + t;         // this thread's point

    const float px = pos[gi * 3 + 0];
    const float py = pos[gi * 3 + 1];
    const float pz = pos[gi * 3 + 2];
    float dmin = CUDART_INF_F;

    if (t == 0) { s_c[0] = pos[0]; s_c[1] = pos[1]; s_c[2] = pos[2]; }
    __syncthreads();

    for (int it = 1; it < MCTR; ++it) {
        const int p = it & 1;

        // exact reference arithmetic: ((dx*dx + dy*dy) + dz*dz), all rn, no FMA
        float dx = px - s_c[0], dy = py - s_c[1], dz = pz - s_c[2];
        float d = __fadd_rn(__fadd_rn(__fmul_rn(dx, dx), __fmul_rn(dy, dy)),
                            __fmul_rn(dz, dz));
        dmin = fminf(dmin, d);

        // warp argmax: max value (nonneg float bits monotone as u32), then min index
        unsigned vb   = __float_as_uint(dmin);
        unsigned wmax = __reduce_max_sync(0xffffffffu, vb);
        int cand = (vb == wmax) ? gi : 0x7fffffff;
        int wi   = __reduce_min_sync(0xffffffffu, cand);
        int wl   = wi & 31;                       // winner lane in this warp
        float wx = __shfl_sync(0xffffffffu, px, wl);
        float wy = __shfl_sync(0xffffffffu, py, wl);
        float wz = __shfl_sync(0xffffffffu, pz, wl);
        if (lane == 0) {
            s_wv[w] = wmax; s_wi[w] = wi;
            s_wx[w] = wx;   s_wy[w] = wy; s_wz[w] = wz;
        }
        __syncthreads();   // A: 32 warp partials ready

        if (w == 0) {
            // block-level reduce over exactly 32 warp partials
            unsigned v  = s_wv[lane];
            int      i2 = s_wi[lane];
            unsigned bmax = __reduce_max_sync(0xffffffffu, v);
            int c2 = (v == bmax) ? i2 : 0x7fffffff;
            int bi = __reduce_min_sync(0xffffffffu, c2);
            int c3 = (v == bmax && i2 == bi) ? lane : 63;
            int l2 = __reduce_min_sync(0xffffffffu, c3);
            float bx = __shfl_sync(0xffffffffu, s_wx[lane], l2);
            float by = __shfl_sync(0xffffffffu, s_wy[lane], l2);
            float bz = __shfl_sync(0xffffffffu, s_wz[lane], l2);

            if (lane == 0) {
                unsigned long long key =
                    ((unsigned long long)bmax << 32) | (unsigned)(0xffffffffu - (unsigned)bi);
                unsigned long long xy =
                    ((unsigned long long)__float_as_uint(bx) << 32) | __float_as_uint(by);
                unsigned long long zt =
                    ((unsigned long long)__float_as_uint(bz) << 32) | (unsigned)it;
                st_relaxed_u64(&g_slot[p][bid][0], key);
                st_relaxed_u64(&g_slot[p][bid][1], xy);
                st_release_u64(&g_slot[p][bid][2], zt);   // tag released last
            }

            // every block reduces all G partials itself (single cross-SM round trip)
            const int src = lane & (G - 1);
            unsigned long long zt;
            int spins = 0;
            for (;;) {
                zt = ld_acquire_u64(&g_slot[p][src][2]);
                if ((unsigned)zt == (unsigned)it) break;
                if (++spins > 1024) { __nanosleep(64); }   // cold-path backoff only
            }
            unsigned long long key = ld_relaxed_u64(&g_slot[p][src][0]);
            unsigned long long xy  = ld_relaxed_u64(&g_slot[p][src][1]);

            unsigned vb2  = (unsigned)(key >> 32);
            unsigned gmax = __reduce_max_sync(0xffffffffu, vb2);
            unsigned inv  = (vb2 == gmax) ? (unsigned)key : 0u;   // 0xffffffff - idx
            unsigned ginv = __reduce_max_sync(0xffffffffu, inv);  // -> min idx
            int gbi = (int)(0xffffffffu - ginv);
            int c4  = (vb2 == gmax && (unsigned)key == ginv) ? lane : 63;
            int l3  = __reduce_min_sync(0xffffffffu, c4);
            float cx = __shfl_sync(0xffffffffu, __uint_as_float((unsigned)(xy >> 32)), l3);
            float cy = __shfl_sync(0xffffffffu, __uint_as_float((unsigned)xy),         l3);
            float cz = __shfl_sync(0xffffffffu, __uint_as_float((unsigned)(zt >> 32)), l3);
            if (lane == 0) {
                s_c[0] = cx; s_c[1] = cy; s_c[2] = cz;
                if (bid == 0) g_idx[it] = gbi;
            }
        }
        __syncthreads();   // B: new center visible to all warps
    }
}

// ---------------- Stage 2: ball query ----------------
#define CHUNK 2048
__global__ __launch_bounds__(256)
void nbr_kernel(const float* __restrict__ pos)
{
    __shared__ float sx[CHUNK], sy[CHUNK], sz[CHUNK];
    __shared__ int   s_ci[8][MAXC];
    __shared__ float s_cd[8][MAXC];

    const int tid  = threadIdx.x;
    const int w    = tid >> 5;
    const int lane = tid & 31;
    const int m    = blockIdx.x * 8 + w;

    const int cidx = g_idx[m];
    const float cx = pos[cidx * 3 + 0];
    const float cy = pos[cidx * 3 + 1];
    const float cz = pos[cidx * 3 + 2];

    int cnt = 0;
    for (int base = 0; base < NPTS; base += CHUNK) {
        __syncthreads();
        for (int i = tid; i < CHUNK; i += 256) {
            sx[i] = pos[(base + i) * 3 + 0];
            sy[i] = pos[(base + i) * 3 + 1];
            sz[i] = pos[(base + i) * 3 + 2];
        }
        __syncthreads();
        for (int i = lane; i < CHUNK; i += 32) {
            float dx = sx[i] - cx, dy = sy[i] - cy, dz = sz[i] - cz;
            float d2 = __fadd_rn(__fadd_rn(__fmul_rn(dx, dx), __fmul_rn(dy, dy)),
                                 __fmul_rn(dz, dz));
            bool in = (d2 <= RAD2);
            unsigned mk = __ballot_sync(0xffffffffu, in);
            int slot = cnt + __popc(mk & ((1u << lane) - 1u));
            if (in && slot < MAXC) { s_ci[w][slot] = base + i; s_cd[w][slot] = d2; }
            cnt += __popc(mk);
        }
    }
    cnt = min(cnt, MAXC);

    if (cnt <= KNBR) {
        if (lane < cnt) g_nbr[m * KNBR + lane] = s_ci[w][lane];
        if (lane == 0)  g_cnt[m] = cnt;
    } else {
        for (int c = lane; c < cnt; c += 32) {
            float d = s_cd[w][c];
            int  ii = s_ci[w][c];
            int r = 0;
            for (int o = 0; o < cnt; ++o) {
                float d2o = s_cd[w][o];
                r += (d2o < d) || (d2o == d && s_ci[w][o] < ii);
            }
            if (r < KNBR) g_nbr[m * KNBR + r] = ii;
        }
        if (lane == 0) g_cnt[m] = KNBR;
    }
}

// ---------------- Stage 3: per-edge MLP + masked max aggregation ----------------
__global__ __launch_bounds__(256)
void mlp_kernel(const float* __restrict__ feat,
                const float* __restrict__ pos,
                const float* __restrict__ W1, const float* __restrict__ b1,
                const float* __restrict__ W2, const float* __restrict__ b2,
                const float* __restrict__ W3, const float* __restrict__ b3,
                float* __restrict__ out)
{
    __shared__ float xb[32][68];
    __shared__ float h1[32][64];
    __shared__ float h2[32][64];
    __shared__ float h3[32][128];

    const int m    = blockIdx.x;
    const int tid  = threadIdx.x;
    const int w    = tid >> 5;
    const int lane = tid & 31;
    const int cnt  = g_cnt[m];

    const int cidx = g_idx[m];
    const float cx = pos[cidx * 3 + 0];
    const float cy = pos[cidx * 3 + 1];
    const float cz = pos[cidx * 3 + 2];

    for (int k = w; k < cnt; k += 8) {
        int j = g_nbr[m * KNBR + k];
        xb[k][lane]      = feat[j * FIN + lane];
        xb[k][lane + 32] = feat[j * FIN + lane + 32];
        if (lane == 0) {
            xb[k][64] = pos[j * 3 + 0] - cx;
            xb[k][65] = pos[j * 3 + 1] - cy;
            xb[k][66] = pos[j * 3 + 2] - cz;
        }
    }
    __syncthreads();

    for (int p = tid; p < cnt * 64; p += 256) {
        int k = p >> 6, o = p & 63;
        float acc = b1[o];
        #pragma unroll
        for (int i = 0; i < 67; ++i)
            acc = fmaf(xb[k][i], W1[i * 64 + o], acc);
        h1[k][o] = fmaxf(acc, 0.0f);
    }
    __syncthreads();

    for (int p = tid; p < cnt * 64; p += 256) {
        int k = p >> 6, o = p & 63;
        float acc = b2[o];
        #pragma unroll
        for (int i = 0; i < 64; ++i)
            acc = fmaf(h1[k][i], W2[i * 64 + o], acc);
        h2[k][o] = fmaxf(acc, 0.0f);
    }
    __syncthreads();

    for (int p = tid; p < cnt * 128; p += 256) {
        int k = p >> 7, o = p & 127;
        float acc = b3[o];
        #pragma unroll
        for (int i = 0; i < 64; ++i)
            acc = fmaf(h2[k][i], W3[i * 128 + o], acc);
        h3[k][o] = fmaxf(acc, 0.0f);
    }
    __syncthreads();

    if (tid < 128) {
        float mx = -CUDART_INF_F;
        for (int k = 0; k < cnt; ++k) mx = fmaxf(mx, h3[k][tid]);
        out[m * 128 + tid] = mx;
    }
}

// ---------------- Stage 4: tail outputs ----------------
__global__ void tail_kernel(const float* __restrict__ pos, float* __restrict__ out,
                            int out_size)
{
    int m = blockIdx.x * blockDim.x + threadIdx.x;
    if (m >= MCTR) return;
    const int base = MCTR * 128;
    if (out_size >= base + 3 * MCTR) {
        int j = g_idx[m];
        out[base + 3 * m + 0] = pos[3 * j + 0];
        out[base + 3 * m + 1] = pos[3 * j + 1];
        out[base + 3 * m + 2] = pos[3 * j + 2];
    }
    if (out_size >= base + 3 * MCTR + MCTR) {
        out[base + 3 * MCTR + m] = 0.0f;
    }
}

extern "C" void kernel_launch(void* const* d_in, const int* in_sizes, int n_in,
                              void* d_out, int out_size)
{
    const float* feat = (const float*)d_in[0];
    const float* pos  = (const float*)d_in[1];
    const float* W1 = (const float*)d_in[3];
    const float* b1 = (const float*)d_in[4];
    const float* W2 = (const float*)d_in[5];
    const float* b2 = (const float*)d_in[6];
    const float* W3 = (const float*)d_in[7];
    const float* b3 = (const float*)d_in[8];
    float* out = (float*)d_out;

    fps_init_kernel<<<1, 32>>>();
    fps_kernel<<<G, TFPS>>>(pos);
    nbr_kernel<<<MCTR / 8, 256>>>(pos);
    mlp_kernel<<<MCTR, 256>>>(feat, pos, W1, b1, W2, b2, W3, b3, out);
    tail_kernel<<<(MCTR + 255) / 256, 256>>>(pos, out, out_size);
}

// round 5
// speedup vs baseline: 2.0256x; 1.0160x over previous
#include <cuda_runtime.h>
#include <cuda_bf16.h>
#include <math_constants.h>

#define NPTS 16384
#define MCTR 4096
#define KNBR 32
#define FIN  64
#define RAD2 0.25f
#define MAXC 64

#define G    16      // FPS blocks (co-resident, 1 per SM)
#define TFPS 1024    // threads per FPS block; G*TFPS == NPTS (1 point/thread)

// ---------------- device scratch (no allocations allowed) ----------------
__device__ int g_idx[MCTR];
__device__ int g_nbr[MCTR * KNBR];
__device__ int g_cnt[MCTR];

// FPS exchange: ONE u64 per (parity, block), each on its own 128B line.
//   key = bits(val)<<32 | (0x3FFF - idx)<<12 | tag(12 bits = iteration)
// tag==it in [1,4095]; 0 never matches. Single 8B load = tag + payload atomically.
struct __align__(128) Slot { unsigned long long v; unsigned long long pad[15]; };
__device__ Slot g_slot[2][G];

__global__ void fps_init_kernel()
{
    int t = threadIdx.x;
    if (t < G) { g_slot[0][t].v = 0ull; g_slot[1][t].v = 0ull; }
    if (t == 0) g_idx[0] = 0;
}

__device__ __forceinline__ void st_release_u64(unsigned long long* p, unsigned long long v)
{
    asm volatile("st.release.gpu.global.u64 [%0], %1;" :: "l"(p), "l"(v) : "memory");
}
__device__ __forceinline__ unsigned long long ld_acquire_u64(const unsigned long long* p)
{
    unsigned long long v;
    asm volatile("ld.acquire.gpu.global.u64 %0, [%1];" : "=l"(v) : "l"(p) : "memory");
    return v;
}

// ---------------- Stage 1: cooperative multi-SM FPS ----------------
// Dynamic smem: s_x[NPTS], s_y[NPTS], s_z[NPTS] (192KB) for O(30cyc) center lookup.
__global__ __launch_bounds__(TFPS, 1)
void fps_kernel(const float* __restrict__ pos)
{
    extern __shared__ float s_tab[];
    float* s_x = s_tab;
    float* s_y = s_tab + NPTS;
    float* s_z = s_tab + 2 * NPTS;

    __shared__ unsigned long long s_wkey[32];
    __shared__ int s_widx;

    const int t    = threadIdx.x;
    const int bid  = blockIdx.x;
    const int w    = t >> 5;
    const int lane = t & 31;
    const int gi   = bid * TFPS + t;         // this thread's point

    // fill the smem coordinate table (one-time)
    for (int i = t; i < NPTS; i += TFPS) {
        s_x[i] = pos[i * 3 + 0];
        s_y[i] = pos[i * 3 + 1];
        s_z[i] = pos[i * 3 + 2];
    }
    __syncthreads();

    const float px = s_x[gi];
    const float py = s_y[gi];
    const float pz = s_z[gi];
    float dmin = CUDART_INF_F;
    float cx = s_x[0], cy = s_y[0], cz = s_z[0];

    for (int it = 1; it < MCTR; ++it) {
        const int p = it & 1;

        // exact reference arithmetic: ((dx*dx + dy*dy) + dz*dz), all rn, no FMA
        float dx = px - cx, dy = py - cy, dz = pz - cz;
        float d = __fadd_rn(__fadd_rn(__fmul_rn(dx, dx), __fmul_rn(dy, dy)),
                            __fmul_rn(dz, dz));
        dmin = fminf(dmin, d);

        // warp argmax: max value (nonneg float bits monotone as u32), then min index
        unsigned vb   = __float_as_uint(dmin);
        unsigned wmax = __reduce_max_sync(0xffffffffu, vb);
        int cand = (vb == wmax) ? gi : 0x7fffffff;
        int wi   = __reduce_min_sync(0xffffffffu, cand);
        if (lane == 0)
            s_wkey[w] = ((unsigned long long)wmax << 32)
                      | ((unsigned long long)(0x3FFFu - (unsigned)wi) << 12);
        __syncthreads();   // A: 32 warp partial keys ready

        if (w == 0) {
            // block reduce over 32 u64 keys: max hi, then max lo among hi-ties
            unsigned long long k = s_wkey[lane];
            unsigned hi  = (unsigned)(k >> 32);
            unsigned bhi = __reduce_max_sync(0xffffffffu, hi);
            unsigned lo  = (hi == bhi) ? (unsigned)k : 0u;
            unsigned blo = __reduce_max_sync(0xffffffffu, lo);

            if (lane == 0)
                st_release_u64(&g_slot[p][bid].v,
                               (((unsigned long long)bhi << 32) | blo | (unsigned)it));

            // poll all 16 slots (2 lanes per slot); tag+payload in ONE 8B load
            const unsigned long long* src = &g_slot[p][lane & (G - 1)].v;
            unsigned long long r;
            int spins = 0;
            for (;;) {
                r = ld_acquire_u64(src);
                if ((unsigned)(r & 0xFFFu) == (unsigned)it) break;
                if (++spins > 4096) __nanosleep(64);   // cold-path safety only
            }
            unsigned hi2  = (unsigned)(r >> 32);
            unsigned gmax = __reduce_max_sync(0xffffffffu, hi2);
            unsigned lo2  = (hi2 == gmax) ? (unsigned)r : 0u;
            unsigned glo  = __reduce_max_sync(0xffffffffu, lo2);
            int gidx = (int)(0x3FFFu - ((glo >> 12) & 0x3FFFu));
            if (lane == 0) {
                s_widx = gidx;
                if (bid == 0) g_idx[it] = gidx;
            }
        }
        __syncthreads();   // B: winner index visible

        int ci = s_widx;               // broadcast LDS, all threads
        cx = s_x[ci]; cy = s_y[ci]; cz = s_z[ci];
    }
}

// ---------------- Stage 2: ball query ----------------
#define CHUNK 2048
__global__ __launch_bounds__(256)
void nbr_kernel(const float* __restrict__ pos)
{
    __shared__ float sx[CHUNK], sy[CHUNK], sz[CHUNK];
    __shared__ int   s_ci[8][MAXC];
    __shared__ float s_cd[8][MAXC];

    const int tid  = threadIdx.x;
    const int w    = tid >> 5;
    const int lane = tid & 31;
    const int m    = blockIdx.x * 8 + w;

    const int cidx = g_idx[m];
    const float cx = pos[cidx * 3 + 0];
    const float cy = pos[cidx * 3 + 1];
    const float cz = pos[cidx * 3 + 2];

    int cnt = 0;
    for (int base = 0; base < NPTS; base += CHUNK) {
        __syncthreads();
        for (int i = tid; i < CHUNK; i += 256) {
            sx[i] = pos[(base + i) * 3 + 0];
            sy[i] = pos[(base + i) * 3 + 1];
            sz[i] = pos[(base + i) * 3 + 2];
        }
        __syncthreads();
        for (int i = lane; i < CHUNK; i += 32) {
            float dx = sx[i] - cx, dy = sy[i] - cy, dz = sz[i] - cz;
            float d2 = __fadd_rn(__fadd_rn(__fmul_rn(dx, dx), __fmul_rn(dy, dy)),
                                 __fmul_rn(dz, dz));
            bool in = (d2 <= RAD2);
            unsigned mk = __ballot_sync(0xffffffffu, in);
            int slot = cnt + __popc(mk & ((1u << lane) - 1u));
            if (in && slot < MAXC) { s_ci[w][slot] = base + i; s_cd[w][slot] = d2; }
            cnt += __popc(mk);
        }
    }
    cnt = min(cnt, MAXC);

    if (cnt <= KNBR) {
        if (lane < cnt) g_nbr[m * KNBR + lane] = s_ci[w][lane];
        if (lane == 0)  g_cnt[m] = cnt;
    } else {
        for (int c = lane; c < cnt; c += 32) {
            float d = s_cd[w][c];
            int  ii = s_ci[w][c];
            int r = 0;
            for (int o = 0; o < cnt; ++o) {
                float d2o = s_cd[w][o];
                r += (d2o < d) || (d2o == d && s_ci[w][o] < ii);
            }
            if (r < KNBR) g_nbr[m * KNBR + r] = ii;
        }
        if (lane == 0) g_cnt[m] = KNBR;
    }
}

// ---------------- Stage 3: per-edge MLP + masked max aggregation ----------------
__global__ __launch_bounds__(256)
void mlp_kernel(const float* __restrict__ feat,
                const float* __restrict__ pos,
                const float* __restrict__ W1, const float* __restrict__ b1,
                const float* __restrict__ W2, const float* __restrict__ b2,
                const float* __restrict__ W3, const float* __restrict__ b3,
                float* __restrict__ out)
{
    __shared__ float xb[32][68];
    __shared__ float h1[32][64];
    __shared__ float h2[32][64];
    __shared__ float h3[32][128];

    const int m    = blockIdx.x;
    const int tid  = threadIdx.x;
    const int w    = tid >> 5;
    const int lane = tid & 31;
    const int cnt  = g_cnt[m];

    const int cidx = g_idx[m];
    const float cx = pos[cidx * 3 + 0];
    const float cy = pos[cidx * 3 + 1];
    const float cz = pos[cidx * 3 + 2];

    for (int k = w; k < cnt; k += 8) {
        int j = g_nbr[m * KNBR + k];
        xb[k][lane]      = feat[j * FIN + lane];
        xb[k][lane + 32] = feat[j * FIN + lane + 32];
        if (lane == 0) {
            xb[k][64] = pos[j * 3 + 0] - cx;
            xb[k][65] = pos[j * 3 + 1] - cy;
            xb[k][66] = pos[j * 3 + 2] - cz;
        }
    }
    __syncthreads();

    for (int p = tid; p < cnt * 64; p += 256) {
        int k = p >> 6, o = p & 63;
        float acc = b1[o];
        #pragma unroll
        for (int i = 0; i < 67; ++i)
            acc = fmaf(xb[k][i], W1[i * 64 + o], acc);
        h1[k][o] = fmaxf(acc, 0.0f);
    }
    __syncthreads();

    for (int p = tid; p < cnt * 64; p += 256) {
        int k = p >> 6, o = p & 63;
        float acc = b2[o];
        #pragma unroll
        for (int i = 0; i < 64; ++i)
            acc = fmaf(h1[k][i], W2[i * 64 + o], acc);
        h2[k][o] = fmaxf(acc, 0.0f);
    }
    __syncthreads();

    for (int p = tid; p < cnt * 128; p += 256) {
        int k = p >> 7, o = p & 127;
        float acc = b3[o];
        #pragma unroll
        for (int i = 0; i < 64; ++i)
            acc = fmaf(h2[k][i], W3[i * 128 + o], acc);
        h3[k][o] = fmaxf(acc, 0.0f);
    }
    __syncthreads();

    if (tid < 128) {
        float mx = -CUDART_INF_F;
        for (int k = 0; k < cnt; ++k) mx = fmaxf(mx, h3[k][tid]);
        out[m * 128 + tid] = mx;
    }
}

// ---------------- Stage 4: tail outputs ----------------
__global__ void tail_kernel(const float* __restrict__ pos, float* __restrict__ out,
                            int out_size)
{
    int m = blockIdx.x * blockDim.x + threadIdx.x;
    if (m >= MCTR) return;
    const int base = MCTR * 128;
    if (out_size >= base + 3 * MCTR) {
        int j = g_idx[m];
        out[base + 3 * m + 0] = pos[3 * j + 0];
        out[base + 3 * m + 1] = pos[3 * j + 1];
        out[base + 3 * m + 2] = pos[3 * j + 2];
    }
    if (out_size >= base + 3 * MCTR + MCTR) {
        out[base + 3 * MCTR + m] = 0.0f;
    }
}

extern "C" void kernel_launch(void* const* d_in, const int* in_sizes, int n_in,
                              void* d_out, int out_size)
{
    const float* feat = (const float*)d_in[0];
    const float* pos  = (const float*)d_in[1];
    const float* W1 = (const float*)d_in[3];
    const float* b1 = (const float*)d_in[4];
    const float* W2 = (const float*)d_in[5];
    const float* b2 = (const float*)d_in[6];
    const float* W3 = (const float*)d_in[7];
    const float* b3 = (const float*)d_in[8];
    float* out = (float*)d_out;

    const size_t fps_smem = 3 * NPTS * sizeof(float);   // 192KB
    cudaFuncSetAttribute(fps_kernel, cudaFuncAttributeMaxDynamicSharedMemorySize,
                         (int)fps_smem);

    fps_init_kernel<<<1, 32>>>();
    fps_kernel<<<G, TFPS, fps_smem>>>(pos);
    nbr_kernel<<<MCTR / 8, 256>>>(pos);
    mlp_kernel<<<MCTR, 256>>>(feat, pos, W1, b1, W2, b2, W3, b3, out);
    tail_kernel<<<(MCTR + 255) / 256, 256>>>(pos, out, out_size);
}

// round 6
// speedup vs baseline: 4.7918x; 2.3657x over previous
#include <cuda_runtime.h>
#include <cuda_bf16.h>
#include <math_constants.h>

#define NPTS 16384
#define MCTR 4096
#define KNBR 32
#define FIN  64
#define RAD2 0.25f
#define MAXC 64

#define CLS  8       // FPS cluster size (CTAs)
#define TFPS 1024    // threads per FPS CTA; CLS*TFPS*2 == NPTS (2 pts/thread)

// ---------------- device scratch (no allocations allowed) ----------------
__device__ int g_idx[MCTR];
__device__ int g_nbr[MCTR * KNBR];
__device__ int g_cnt[MCTR];

__device__ __forceinline__ unsigned smem_u32(const void* p)
{
    unsigned a;
    asm("{ .reg .u64 t; cvta.to.shared.u64 t, %1; cvt.u32.u64 %0, t; }"
        : "=r"(a) : "l"(p));
    return a;
}

// ---------------- Stage 1: cluster-cooperative FPS (DSMEM mailbox exchange) ----------------
// key = bits(val)<<32 | (0x3FFF - idx)<<12 | tag(12 bits = iteration)
// One 8B word: tag + payload arrive atomically; receivers poll LOCAL smem.
__global__ __launch_bounds__(TFPS, 1) __cluster_dims__(CLS, 1, 1)
void fps_kernel(const float* __restrict__ pos)
{
    extern __shared__ float s_tab[];
    float* s_x = s_tab;
    float* s_y = s_tab + NPTS;
    float* s_z = s_tab + 2 * NPTS;

    __shared__ unsigned long long s_mbox[2][CLS];   // [parity][source CTA]
    __shared__ unsigned long long s_wkey[32];
    __shared__ int s_widx;

    const int t    = threadIdx.x;
    const int w    = t >> 5;
    const int lane = t & 31;
    unsigned rank;
    asm("mov.u32 %0, %%cluster_ctarank;" : "=r"(rank));

    // one-time: local coordinate table + mailbox init
    for (int i = t; i < NPTS; i += TFPS) {
        s_x[i] = pos[i * 3 + 0];
        s_y[i] = pos[i * 3 + 1];
        s_z[i] = pos[i * 3 + 2];
    }
    if (t < 2 * CLS) s_mbox[t >> 3][t & (CLS - 1)] = 0ull;
    if (rank == 0 && t == 0) g_idx[0] = 0;
    __syncthreads();
    asm volatile("barrier.cluster.arrive.aligned;" ::: "memory");
    asm volatile("barrier.cluster.wait.aligned;"   ::: "memory");

    const int gi0 = (int)rank * (TFPS * 2) + t;
    const int gi1 = gi0 + TFPS;
    const float px0 = s_x[gi0], py0 = s_y[gi0], pz0 = s_z[gi0];
    const float px1 = s_x[gi1], py1 = s_y[gi1], pz1 = s_z[gi1];
    float dm0 = CUDART_INF_F, dm1 = CUDART_INF_F;
    float cx = s_x[0], cy = s_y[0], cz = s_z[0];

    for (int it = 1; it < MCTR; ++it) {
        const int p = it & 1;

        // exact reference arithmetic: ((dx*dx + dy*dy) + dz*dz), all rn, no FMA
        float dx = px0 - cx, dy = py0 - cy, dz = pz0 - cz;
        float d0 = __fadd_rn(__fadd_rn(__fmul_rn(dx, dx), __fmul_rn(dy, dy)),
                             __fmul_rn(dz, dz));
        dm0 = fminf(dm0, d0);
        dx = px1 - cx; dy = py1 - cy; dz = pz1 - cz;
        float d1 = __fadd_rn(__fadd_rn(__fmul_rn(dx, dx), __fmul_rn(dy, dy)),
                             __fmul_rn(dz, dz));
        dm1 = fminf(dm1, d1);

        // thread-local argmax with first-index (lower gi) tie-break
        float bestv = dm0; int besti = gi0;
        if (dm1 > bestv) { bestv = dm1; besti = gi1; }

        // warp argmax: max value (nonneg float bits monotone as u32), then min index
        unsigned vb   = __float_as_uint(bestv);
        unsigned wmax = __reduce_max_sync(0xffffffffu, vb);
        int cand = (vb == wmax) ? besti : 0x7fffffff;
        int wi   = __reduce_min_sync(0xffffffffu, cand);
        if (lane == 0)
            s_wkey[w] = ((unsigned long long)wmax << 32)
                      | ((unsigned long long)(0x3FFFu - (unsigned)wi) << 12);
        __syncthreads();   // A: 32 warp partial keys ready

        if (w == 0) {
            // block reduce over 32 u64 keys: max hi, then max lo among hi-ties
            unsigned long long k = s_wkey[lane];
            unsigned hi  = (unsigned)(k >> 32);
            unsigned bhi = __reduce_max_sync(0xffffffffu, hi);
            unsigned lo  = (hi == bhi) ? (unsigned)k : 0u;
            unsigned blo = __reduce_max_sync(0xffffffffu, lo);
            unsigned long long bkey =
                ((unsigned long long)bhi << 32) | blo | (unsigned)it;

            // push our key into every CTA's mailbox (8 remote stores in parallel)
            if (lane < CLS) {
                unsigned la = smem_u32(&s_mbox[p][rank]);
                unsigned ra;
                asm("mapa.shared::cluster.u32 %0, %1, %2;"
                    : "=r"(ra) : "r"(la), "r"(lane));
                asm volatile("st.relaxed.cluster.shared::cluster.b64 [%0], %1;"
                             :: "r"(ra), "l"(bkey) : "memory");
            }

            // poll LOCAL mailbox (29-cycle LDS polls, not 250-cycle L2 polls)
            unsigned pa = smem_u32(&s_mbox[p][lane & (CLS - 1)]);
            unsigned long long r;
            int spins = 0;
            for (;;) {
                asm volatile("ld.volatile.shared.b64 %0, [%1];"
                             : "=l"(r) : "r"(pa) : "memory");
                if ((unsigned)(r & 0xFFFu) == (unsigned)it) break;
                if (++spins > 8192) __nanosleep(32);   // cold-path safety only
            }
            unsigned hi2  = (unsigned)(r >> 32);
            unsigned gmax = __reduce_max_sync(0xffffffffu, hi2);
            unsigned lo2  = (hi2 == gmax) ? (unsigned)r : 0u;
            unsigned glo  = __reduce_max_sync(0xffffffffu, lo2);
            int gidx = (int)(0x3FFFu - ((glo >> 12) & 0x3FFFu));
            if (lane == 0) {
                s_widx = gidx;
                if (rank == 0) g_idx[it] = gidx;   // fire-and-forget STG
            }
        }
        __syncthreads();   // B: winner index visible

        int ci = s_widx;                 // broadcast LDS
        cx = s_x[ci]; cy = s_y[ci]; cz = s_z[ci];
    }

    // no CTA may exit while peers could still target its smem
    asm volatile("barrier.cluster.arrive.aligned;" ::: "memory");
    asm volatile("barrier.cluster.wait.aligned;"   ::: "memory");
}

// ---------------- Stage 2: ball query ----------------
#define CHUNK 2048
__global__ __launch_bounds__(256)
void nbr_kernel(const float* __restrict__ pos)
{
    __shared__ float sx[CHUNK], sy[CHUNK], sz[CHUNK];
    __shared__ int   s_ci[8][MAXC];
    __shared__ float s_cd[8][MAXC];

    const int tid  = threadIdx.x;
    const int w    = tid >> 5;
    const int lane = tid & 31;
    const int m    = blockIdx.x * 8 + w;

    const int cidx = g_idx[m];
    const float cx = pos[cidx * 3 + 0];
    const float cy = pos[cidx * 3 + 1];
    const float cz = pos[cidx * 3 + 2];

    int cnt = 0;
    for (int base = 0; base < NPTS; base += CHUNK) {
        __syncthreads();
        for (int i = tid; i < CHUNK; i += 256) {
            sx[i] = pos[(base + i) * 3 + 0];
            sy[i] = pos[(base + i) * 3 + 1];
            sz[i] = pos[(base + i) * 3 + 2];
        }
        __syncthreads();
        for (int i = lane; i < CHUNK; i += 32) {
            float dx = sx[i] - cx, dy = sy[i] - cy, dz = sz[i] - cz;
            float d2 = __fadd_rn(__fadd_rn(__fmul_rn(dx, dx), __fmul_rn(dy, dy)),
                                 __fmul_rn(dz, dz));
            bool in = (d2 <= RAD2);
            unsigned mk = __ballot_sync(0xffffffffu, in);
            int slot = cnt + __popc(mk & ((1u << lane) - 1u));
            if (in && slot < MAXC) { s_ci[w][slot] = base + i; s_cd[w][slot] = d2; }
            cnt += __popc(mk);
        }
    }
    cnt = min(cnt, MAXC);

    if (cnt <= KNBR) {
        if (lane < cnt) g_nbr[m * KNBR + lane] = s_ci[w][lane];
        if (lane == 0)  g_cnt[m] = cnt;
    } else {
        for (int c = lane; c < cnt; c += 32) {
            float d = s_cd[w][c];
            int  ii = s_ci[w][c];
            int r = 0;
            for (int o = 0; o < cnt; ++o) {
                float d2o = s_cd[w][o];
                r += (d2o < d) || (d2o == d && s_ci[w][o] < ii);
            }
            if (r < KNBR) g_nbr[m * KNBR + r] = ii;
        }
        if (lane == 0) g_cnt[m] = KNBR;
    }
}

// ---------------- Stage 3: per-edge MLP + masked max aggregation ----------------
__global__ __launch_bounds__(256)
void mlp_kernel(const float* __restrict__ feat,
                const float* __restrict__ pos,
                const float* __restrict__ W1, const float* __restrict__ b1,
                const float* __restrict__ W2, const float* __restrict__ b2,
                const float* __restrict__ W3, const float* __restrict__ b3,
                float* __restrict__ out)
{
    __shared__ float xb[32][68];
    __shared__ float h1[32][64];
    __shared__ float h2[32][64];
    __shared__ float h3[32][128];

    const int m    = blockIdx.x;
    const int tid  = threadIdx.x;
    const int w    = tid >> 5;
    const int lane = tid & 31;
    const int cnt  = g_cnt[m];

    const int cidx = g_idx[m];
    const float cx = pos[cidx * 3 + 0];
    const float cy = pos[cidx * 3 + 1];
    const float cz = pos[cidx * 3 + 2];

    for (int k = w; k < cnt; k += 8) {
        int j = g_nbr[m * KNBR + k];
        xb[k][lane]      = feat[j * FIN + lane];
        xb[k][lane + 32] = feat[j * FIN + lane + 32];
        if (lane == 0) {
            xb[k][64] = pos[j * 3 + 0] - cx;
            xb[k][65] = pos[j * 3 + 1] - cy;
            xb[k][66] = pos[j * 3 + 2] - cz;
        }
    }
    __syncthreads();

    for (int p = tid; p < cnt * 64; p += 256) {
        int k = p >> 6, o = p & 63;
        float acc = b1[o];
        #pragma unroll
        for (int i = 0; i < 67; ++i)
            acc = fmaf(xb[k][i], W1[i * 64 + o], acc);
        h1[k][o] = fmaxf(acc, 0.0f);
    }
    __syncthreads();

    for (int p = tid; p < cnt * 64; p += 256) {
        int k = p >> 6, o = p & 63;
        float acc = b2[o];
        #pragma unroll
        for (int i = 0; i < 64; ++i)
            acc = fmaf(h1[k][i], W2[i * 64 + o], acc);
        h2[k][o] = fmaxf(acc, 0.0f);
    }
    __syncthreads();

    for (int p = tid; p < cnt * 128; p += 256) {
        int k = p >> 7, o = p & 127;
        float acc = b3[o];
        #pragma unroll
        for (int i = 0; i < 64; ++i)
            acc = fmaf(h2[k][i], W3[i * 128 + o], acc);
        h3[k][o] = fmaxf(acc, 0.0f);
    }
    __syncthreads();

    if (tid < 128) {
        float mx = -CUDART_INF_F;
        for (int k = 0; k < cnt; ++k) mx = fmaxf(mx, h3[k][tid]);
        out[m * 128 + tid] = mx;
    }
}

// ---------------- Stage 4: tail outputs ----------------
__global__ void tail_kernel(const float* __restrict__ pos, float* __restrict__ out,
                            int out_size)
{
    int m = blockIdx.x * blockDim.x + threadIdx.x;
    if (m >= MCTR) return;
    const int base = MCTR * 128;
    if (out_size >= base + 3 * MCTR) {
        int j = g_idx[m];
        out[base + 3 * m + 0] = pos[3 * j + 0];
        out[base + 3 * m + 1] = pos[3 * j + 1];
        out[base + 3 * m + 2] = pos[3 * j + 2];
    }
    if (out_size >= base + 3 * MCTR + MCTR) {
        out[base + 3 * MCTR + m] = 0.0f;
    }
}

extern "C" void kernel_launch(void* const* d_in, const int* in_sizes, int n_in,
                              void* d_out, int out_size)
{
    const float* feat = (const float*)d_in[0];
    const float* pos  = (const float*)d_in[1];
    const float* W1 = (const float*)d_in[3];
    const float* b1 = (const float*)d_in[4];
    const float* W2 = (const float*)d_in[5];
    const float* b2 = (const float*)d_in[6];
    const float* W3 = (const float*)d_in[7];
    const float* b3 = (const float*)d_in[8];
    float* out = (float*)d_out;

    const size_t fps_smem = 3 * NPTS * sizeof(float);   // 192KB
    static int configured = 0;
    if (!configured) {
        cudaFuncSetAttribute(fps_kernel, cudaFuncAttributeMaxDynamicSharedMemorySize,
                             (int)fps_smem);
        configured = 1;
    }

    fps_kernel<<<CLS, TFPS, fps_smem>>>(pos);
    nbr_kernel<<<MCTR / 8, 256>>>(pos);
    mlp_kernel<<<MCTR, 256>>>(feat, pos, W1, b1, W2, b2, W3, b3, out);
    tail_kernel<<<(MCTR + 255) / 256, 256>>>(pos, out, out_size);
}

// round 7
// speedup vs baseline: 5.8741x; 1.2259x over previous
#include <cuda_runtime.h>
#include <cuda_bf16.h>
#include <math_constants.h>

#define NPTS 16384
#define MCTR 4096
#define KNBR 32
#define FIN  64
#define RAD2 0.25f
#define MAXC 64

#define CLS  8       // FPS cluster size (CTAs)
#define TFPS 256     // threads per FPS CTA
#define PPT  8       // points per thread; CLS*TFPS*PPT == NPTS

// ---------------- device scratch (no allocations allowed) ----------------
__device__ int g_idx[MCTR];
__device__ int g_nbr[MCTR * KNBR];
__device__ int g_cnt[MCTR];

__device__ __forceinline__ unsigned smem_u32(const void* p)
{
    unsigned a;
    asm("{ .reg .u64 t; cvta.to.shared.u64 t, %1; cvt.u32.u64 %0, t; }"
        : "=r"(a) : "l"(p));
    return a;
}

// ---------------- Stage 1: cluster-cooperative FPS (DSMEM mailbox exchange) ----------------
// key = bits(val)<<32 | (0x3FFF - idx)<<12 | tag(12 bits = iteration)
// One 8B word: tag + payload arrive atomically; receivers poll LOCAL smem.
__global__ __launch_bounds__(TFPS, 1) __cluster_dims__(CLS, 1, 1)
void fps_kernel(const float* __restrict__ pos)
{
    extern __shared__ float s_tab[];
    float* s_x = s_tab;
    float* s_y = s_tab + NPTS;
    float* s_z = s_tab + 2 * NPTS;

    __shared__ unsigned long long s_mbox[2][CLS];   // [parity][source CTA]
    __shared__ unsigned long long s_wkey[TFPS / 32];
    __shared__ int s_widx;

    const int t    = threadIdx.x;
    const int w    = t >> 5;
    const int lane = t & 31;
    unsigned rank;
    asm("mov.u32 %0, %%cluster_ctarank;" : "=r"(rank));

    // one-time: local coordinate table + mailbox init
    for (int i = t; i < NPTS; i += TFPS) {
        s_x[i] = pos[i * 3 + 0];
        s_y[i] = pos[i * 3 + 1];
        s_z[i] = pos[i * 3 + 2];
    }
    if (t < 2 * CLS) s_mbox[t >> 3][t & (CLS - 1)] = 0ull;
    if (rank == 0 && t == 0) g_idx[0] = 0;
    __syncthreads();
    asm volatile("barrier.cluster.arrive.aligned;" ::: "memory");
    asm volatile("barrier.cluster.wait.aligned;"   ::: "memory");

    // this thread's PPT points: gi = base + t + j*TFPS (ascending in j)
    const int base = (int)rank * (TFPS * PPT) + t;
    float px[PPT], py[PPT], pz[PPT], dmin[PPT];
    #pragma unroll
    for (int j = 0; j < PPT; ++j) {
        int gi = base + j * TFPS;
        px[j] = s_x[gi]; py[j] = s_y[gi]; pz[j] = s_z[gi];
        dmin[j] = CUDART_INF_F;
    }
    float cx = s_x[0], cy = s_y[0], cz = s_z[0];

    for (int it = 1; it < MCTR; ++it) {
        const int p = it & 1;

        // exact reference arithmetic: ((dx*dx + dy*dy) + dz*dz), all rn, no FMA
        // thread-local argmax with first-index tie-break (ascending gi, strict >)
        float bestv = -1.0f;
        int   bestj = 0;
        #pragma unroll
        for (int j = 0; j < PPT; ++j) {
            float dx = px[j] - cx, dy = py[j] - cy, dz = pz[j] - cz;
            float d = __fadd_rn(__fadd_rn(__fmul_rn(dx, dx), __fmul_rn(dy, dy)),
                                __fmul_rn(dz, dz));
            float dm = fminf(dmin[j], d);
            dmin[j] = dm;
            if (dm > bestv) { bestv = dm; bestj = j; }
        }
        int besti = base + bestj * TFPS;

        // warp argmax: max value (nonneg float bits monotone as u32), then min index
        unsigned vb   = __float_as_uint(bestv);
        unsigned wmax = __reduce_max_sync(0xffffffffu, vb);
        int cand = (vb == wmax) ? besti : 0x7fffffff;
        int wi   = __reduce_min_sync(0xffffffffu, cand);
        if (lane == 0)
            s_wkey[w] = ((unsigned long long)wmax << 32)
                      | ((unsigned long long)(0x3FFFu - (unsigned)wi) << 12);
        __syncthreads();   // A: 8 warp partial keys ready

        if (w == 0) {
            // block reduce over 8 u64 keys (lanes replicate every 8; max is idempotent)
            unsigned long long k = s_wkey[lane & (TFPS / 32 - 1)];
            unsigned hi  = (unsigned)(k >> 32);
            unsigned bhi = __reduce_max_sync(0xffffffffu, hi);
            unsigned lo  = (hi == bhi) ? (unsigned)k : 0u;
            unsigned blo = __reduce_max_sync(0xffffffffu, lo);
            unsigned long long bkey =
                ((unsigned long long)bhi << 32) | blo | (unsigned)it;

            // push our key into every CTA's mailbox (8 remote stores in parallel)
            if (lane < CLS) {
                unsigned la = smem_u32(&s_mbox[p][rank]);
                unsigned ra;
                asm("mapa.shared::cluster.u32 %0, %1, %2;"
                    : "=r"(ra) : "r"(la), "r"(lane));
                asm volatile("st.relaxed.cluster.shared::cluster.b64 [%0], %1;"
                             :: "r"(ra), "l"(bkey) : "memory");
            }

            // poll LOCAL mailbox (LDS polls, not L2 polls)
            unsigned pa = smem_u32(&s_mbox[p][lane & (CLS - 1)]);
            unsigned long long r;
            int spins = 0;
            for (;;) {
                asm volatile("ld.volatile.shared.b64 %0, [%1];"
                             : "=l"(r) : "r"(pa) : "memory");
                if ((unsigned)(r & 0xFFFu) == (unsigned)it) break;
                if (++spins > 8192) __nanosleep(32);   // cold-path safety only
            }
            unsigned hi2  = (unsigned)(r >> 32);
            unsigned gmax = __reduce_max_sync(0xffffffffu, hi2);
            unsigned lo2  = (hi2 == gmax) ? (unsigned)r : 0u;
            unsigned glo  = __reduce_max_sync(0xffffffffu, lo2);
            int gidx = (int)(0x3FFFu - ((glo >> 12) & 0x3FFFu));
            if (lane == 0) {
                s_widx = gidx;
                if (rank == 0) g_idx[it] = gidx;   // fire-and-forget STG
            }
        }
        __syncthreads();   // B: winner index visible

        int ci = s_widx;                 // broadcast LDS
        cx = s_x[ci]; cy = s_y[ci]; cz = s_z[ci];
    }

    // no CTA may exit while peers could still target its smem
    asm volatile("barrier.cluster.arrive.aligned;" ::: "memory");
    asm volatile("barrier.cluster.wait.aligned;"   ::: "memory");
}

// ---------------- Stage 2: ball query ----------------
#define CHUNK 2048
__global__ __launch_bounds__(256)
void nbr_kernel(const float* __restrict__ pos)
{
    __shared__ float sx[CHUNK], sy[CHUNK], sz[CHUNK];
    __shared__ int   s_ci[8][MAXC];
    __shared__ float s_cd[8][MAXC];

    const int tid  = threadIdx.x;
    const int w    = tid >> 5;
    const int lane = tid & 31;
    const int m    = blockIdx.x * 8 + w;

    const int cidx = g_idx[m];
    const float cx = pos[cidx * 3 + 0];
    const float cy = pos[cidx * 3 + 1];
    const float cz = pos[cidx * 3 + 2];

    int cnt = 0;
    for (int base = 0; base < NPTS; base += CHUNK) {
        __syncthreads();
        for (int i = tid; i < CHUNK; i += 256) {
            sx[i] = pos[(base + i) * 3 + 0];
            sy[i] = pos[(base + i) * 3 + 1];
            sz[i] = pos[(base + i) * 3 + 2];
        }
        __syncthreads();
        for (int i = lane; i < CHUNK; i += 32) {
            float dx = sx[i] - cx, dy = sy[i] - cy, dz = sz[i] - cz;
            float d2 = __fadd_rn(__fadd_rn(__fmul_rn(dx, dx), __fmul_rn(dy, dy)),
                                 __fmul_rn(dz, dz));
            bool in = (d2 <= RAD2);
            unsigned mk = __ballot_sync(0xffffffffu, in);
            int slot = cnt + __popc(mk & ((1u << lane) - 1u));
            if (in && slot < MAXC) { s_ci[w][slot] = base + i; s_cd[w][slot] = d2; }
            cnt += __popc(mk);
        }
    }
    cnt = min(cnt, MAXC);

    if (cnt <= KNBR) {
        if (lane < cnt) g_nbr[m * KNBR + lane] = s_ci[w][lane];
        if (lane == 0)  g_cnt[m] = cnt;
    } else {
        for (int c = lane; c < cnt; c += 32) {
            float d = s_cd[w][c];
            int  ii = s_ci[w][c];
            int r = 0;
            for (int o = 0; o < cnt; ++o) {
                float d2o = s_cd[w][o];
                r += (d2o < d) || (d2o == d && s_ci[w][o] < ii);
            }
            if (r < KNBR) g_nbr[m * KNBR + r] = ii;
        }
        if (lane == 0) g_cnt[m] = KNBR;
    }
}

// ---------------- Stage 3: per-edge MLP + masked max aggregation ----------------
__global__ __launch_bounds__(256)
void mlp_kernel(const float* __restrict__ feat,
                const float* __restrict__ pos,
                const float* __restrict__ W1, const float* __restrict__ b1,
                const float* __restrict__ W2, const float* __restrict__ b2,
                const float* __restrict__ W3, const float* __restrict__ b3,
                float* __restrict__ out)
{
    __shared__ float xb[32][68];
    __shared__ float h1[32][64];
    __shared__ float h2[32][64];
    __shared__ float h3[32][128];

    const int m    = blockIdx.x;
    const int tid  = threadIdx.x;
    const int w    = tid >> 5;
    const int lane = tid & 31;
    const int cnt  = g_cnt[m];

    const int cidx = g_idx[m];
    const float cx = pos[cidx * 3 + 0];
    const float cy = pos[cidx * 3 + 1];
    const float cz = pos[cidx * 3 + 2];

    for (int k = w; k < cnt; k += 8) {
        int j = g_nbr[m * KNBR + k];
        xb[k][lane]      = feat[j * FIN + lane];
        xb[k][lane + 32] = feat[j * FIN + lane + 32];
        if (lane == 0) {
            xb[k][64] = pos[j * 3 + 0] - cx;
            xb[k][65] = pos[j * 3 + 1] - cy;
            xb[k][66] = pos[j * 3 + 2] - cz;
        }
    }
    __syncthreads();

    for (int p = tid; p < cnt * 64; p += 256) {
        int k = p >> 6, o = p & 63;
        float acc = b1[o];
        #pragma unroll
        for (int i = 0; i < 67; ++i)
            acc = fmaf(xb[k][i], W1[i * 64 + o], acc);
        h1[k][o] = fmaxf(acc, 0.0f);
    }
    __syncthreads();

    for (int p = tid; p < cnt * 64; p += 256) {
        int k = p >> 6, o = p & 63;
        float acc = b2[o];
        #pragma unroll
        for (int i = 0; i < 64; ++i)
            acc = fmaf(h1[k][i], W2[i * 64 + o], acc);
        h2[k][o] = fmaxf(acc, 0.0f);
    }
    __syncthreads();

    for (int p = tid; p < cnt * 128; p += 256) {
        int k = p >> 7, o = p & 127;
        float acc = b3[o];
        #pragma unroll
        for (int i = 0; i < 64; ++i)
            acc = fmaf(h2[k][i], W3[i * 128 + o], acc);
        h3[k][o] = fmaxf(acc, 0.0f);
    }
    __syncthreads();

    if (tid < 128) {
        float mx = -CUDART_INF_F;
        for (int k = 0; k < cnt; ++k) mx = fmaxf(mx, h3[k][tid]);
        out[m * 128 + tid] = mx;
    }
}

// ---------------- Stage 4: tail outputs ----------------
__global__ void tail_kernel(const float* __restrict__ pos, float* __restrict__ out,
                            int out_size)
{
    int m = blockIdx.x * blockDim.x + threadIdx.x;
    if (m >= MCTR) return;
    const int base = MCTR * 128;
    if (out_size >= base + 3 * MCTR) {
        int j = g_idx[m];
        out[base + 3 * m + 0] = pos[3 * j + 0];
        out[base + 3 * m + 1] = pos[3 * j + 1];
        out[base + 3 * m + 2] = pos[3 * j + 2];
    }
    if (out_size >= base + 3 * MCTR + MCTR) {
        out[base + 3 * MCTR + m] = 0.0f;
    }
}

extern "C" void kernel_launch(void* const* d_in, const int* in_sizes, int n_in,
                              void* d_out, int out_size)
{
    const float* feat = (const float*)d_in[0];
    const float* pos  = (const float*)d_in[1];
    const float* W1 = (const float*)d_in[3];
    const float* b1 = (const float*)d_in[4];
    const float* W2 = (const float*)d_in[5];
    const float* b2 = (const float*)d_in[6];
    const float* W3 = (const float*)d_in[7];
    const float* b3 = (const float*)d_in[8];
    float* out = (float*)d_out;

    const size_t fps_smem = 3 * NPTS * sizeof(float);   // 192KB
    cudaFuncSetAttribute(fps_kernel, cudaFuncAttributeMaxDynamicSharedMemorySize,
                         (int)fps_smem);

    fps_kernel<<<CLS, TFPS, fps_smem>>>(pos);
    nbr_kernel<<<MCTR / 8, 256>>>(pos);
    mlp_kernel<<<MCTR, 256>>>(feat, pos, W1, b1, W2, b2, W3, b3, out);
    tail_kernel<<<(MCTR + 255) / 256, 256>>>(pos, out, out_size);
}